// round 17
// baseline (speedup 1.0000x reference)
#include <cuda_runtime.h>
#include <math.h>
#include <stdint.h>

#define N_SAMP 1024
#define D      16384
#define WH     128
#define SA     130   // attn smem stride (words); 2*tx mod 32 distinct -> conflict-free LDS.64
#define GSA    18    // gram stage row stride (words)

typedef unsigned long long ull;

// ---- device scratch (no allocations allowed) ----
__device__ float g_gram[N_SAMP * N_SAMP];
__device__ float g_part[144 * 16384];      // split-K partial tiles
__device__ float g_sq[N_SAMP];
__device__ int   g_hp[N_SAMP];
__device__ int   g_hn[N_SAMP];
__device__ float g_dd[4 * N_SAMP];         // per half-block partial dist^2

// ---- packed fp32x2 FMA (Blackwell dual fp32; exact fp32 math) ----
__device__ __forceinline__ void ffma2(ull& d, ull a, ull b) {
    asm("fma.rn.f32x2 %0, %1, %2, %0;" : "+l"(d) : "l"(a), "l"(b));
}
__device__ __forceinline__ float f2sum(ull v) {
    return __uint_as_float((unsigned)(v & 0xFFFFFFFFu)) +
           __uint_as_float((unsigned)(v >> 32));
}

// ===========================================================================
// Kernel 2: Gram GEMM with FFMA2 (unchanged: ~97% of FFMA2 floor).
// ===========================================================================
__global__ __launch_bounds__(256, 1)
void gram_f2(const float* __restrict__ X) {
    __shared__ __align__(16) float As[2][128 * GSA];
    __shared__ __align__(16) float Bs[2][128 * GSA];

    const int tid = threadIdx.x;
    const int tx  = tid & 15;
    const int ty  = tid >> 4;

    int blk = blockIdx.x;
    int split = blk / 36;
    int tile  = blk % 36;
    int r = tile, bi = 0;
    while (r >= 8 - bi) { r -= 8 - bi; bi++; }
    int bj = bi + r;

    const float* Ag = X + (size_t)(bi * 128) * D + split * 4096;
    const float* Bg = X + (size_t)(bj * 128) * D + split * 4096;

    const int lr0 = tid >> 2;
    const int lr1 = lr0 + 64;
    const int lc  = (tid & 3) << 2;

    ull acc[8][8];
#pragma unroll
    for (int m = 0; m < 8; m++)
#pragma unroll
        for (int n = 0; n < 8; n++) acc[m][n] = 0ull;

    float4 pa0 = *(const float4*)(Ag + (size_t)lr0 * D + lc);
    float4 pa1 = *(const float4*)(Ag + (size_t)lr1 * D + lc);
    float4 pb0 = *(const float4*)(Bg + (size_t)lr0 * D + lc);
    float4 pb1 = *(const float4*)(Bg + (size_t)lr1 * D + lc);
    *(float2*)&As[0][lr0 * GSA + lc]     = make_float2(pa0.x, pa0.y);
    *(float2*)&As[0][lr0 * GSA + lc + 2] = make_float2(pa0.z, pa0.w);
    *(float2*)&As[0][lr1 * GSA + lc]     = make_float2(pa1.x, pa1.y);
    *(float2*)&As[0][lr1 * GSA + lc + 2] = make_float2(pa1.z, pa1.w);
    *(float2*)&Bs[0][lr0 * GSA + lc]     = make_float2(pb0.x, pb0.y);
    *(float2*)&Bs[0][lr0 * GSA + lc + 2] = make_float2(pb0.z, pb0.w);
    *(float2*)&Bs[0][lr1 * GSA + lc]     = make_float2(pb1.x, pb1.y);
    *(float2*)&Bs[0][lr1 * GSA + lc + 2] = make_float2(pb1.z, pb1.w);
    __syncthreads();

    const int NC = 4096 / 16;
    int cur = 0;
    for (int c = 0; c < NC; c++) {
        bool more = (c + 1) < NC;
        if (more) {
            int kk = (c + 1) * 16;
            pa0 = *(const float4*)(Ag + (size_t)lr0 * D + kk + lc);
            pa1 = *(const float4*)(Ag + (size_t)lr1 * D + kk + lc);
            pb0 = *(const float4*)(Bg + (size_t)lr0 * D + kk + lc);
            pb1 = *(const float4*)(Bg + (size_t)lr1 * D + kk + lc);
        }
#pragma unroll
        for (int kp = 0; kp < 8; kp++) {
            ull av[8], bv[8];
#pragma unroll
            for (int m = 0; m < 8; m++)
                av[m] = *(const ull*)&As[cur][(ty + 16 * m) * GSA + 2 * kp];
#pragma unroll
            for (int n = 0; n < 8; n++)
                bv[n] = *(const ull*)&Bs[cur][(tx + 16 * n) * GSA + 2 * kp];
#pragma unroll
            for (int m = 0; m < 8; m++)
#pragma unroll
                for (int n = 0; n < 8; n++) ffma2(acc[m][n], av[m], bv[n]);
        }
        if (more) {
            int nxt = cur ^ 1;
            *(float2*)&As[nxt][lr0 * GSA + lc]     = make_float2(pa0.x, pa0.y);
            *(float2*)&As[nxt][lr0 * GSA + lc + 2] = make_float2(pa0.z, pa0.w);
            *(float2*)&As[nxt][lr1 * GSA + lc]     = make_float2(pa1.x, pa1.y);
            *(float2*)&As[nxt][lr1 * GSA + lc + 2] = make_float2(pa1.z, pa1.w);
            *(float2*)&Bs[nxt][lr0 * GSA + lc]     = make_float2(pb0.x, pb0.y);
            *(float2*)&Bs[nxt][lr0 * GSA + lc + 2] = make_float2(pb0.z, pb0.w);
            *(float2*)&Bs[nxt][lr1 * GSA + lc]     = make_float2(pb1.x, pb1.y);
            *(float2*)&Bs[nxt][lr1 * GSA + lc + 2] = make_float2(pb1.z, pb1.w);
            __syncthreads();
            cur = nxt;
        }
    }

    float* dst = g_part + (size_t)blk * 16384;
#pragma unroll
    for (int m = 0; m < 8; m++)
#pragma unroll
        for (int n = 0; n < 8; n++)
            dst[(ty + 16 * m) * 128 + (tx + 16 * n)] = f2sum(acc[m][n]);
}

// ===========================================================================
// Kernel 2b: reduce split-K partials, write G, mirror, and diagonal -> g_sq
// ===========================================================================
__global__ void gram_reduce() {
    int tile = blockIdx.x;
    int r = tile, bi = 0;
    while (r >= 8 - bi) { r -= 8 - bi; bi++; }
    int bj = bi + r;
    const float* p0 = g_part + (size_t)(0 * 36 + tile) * 16384;
    const float* p1 = g_part + (size_t)(1 * 36 + tile) * 16384;
    const float* p2 = g_part + (size_t)(2 * 36 + tile) * 16384;
    const float* p3 = g_part + (size_t)(3 * 36 + tile) * 16384;
    for (int u = threadIdx.x; u < 16384; u += 256) {
        float s = p0[u] + p1[u] + p2[u] + p3[u];
        int rr = u >> 7, cc = u & 127;
        int i = bi * 128 + rr, j = bj * 128 + cc;
        g_gram[i * N_SAMP + j] = s;
        if (bi != bj) g_gram[j * N_SAMP + i] = s;
        else if (rr == cc) g_sq[i] = s;
    }
}

// ===========================================================================
// Kernel 3: hard mining
// ===========================================================================
__global__ void mine_kernel(const int* __restrict__ targets) {
    int i   = blockIdx.x;
    int tid = threadIdx.x;
    int tg  = targets[i];

    float bpv = -3.0e38f; int bpi = 0;
    float bnv =  3.0e38f; int bni = 0;
    for (int j = tid; j < N_SAMP; j += 256) {
        float val = g_sq[j] - 2.f * g_gram[i * N_SAMP + j];
        if (targets[j] == tg) {
            if (val > bpv || (val == bpv && j < bpi)) { bpv = val; bpi = j; }
        } else {
            if (val < bnv || (val == bnv && j < bni)) { bnv = val; bni = j; }
        }
    }
    __shared__ float spv[256]; __shared__ int spi[256];
    __shared__ float snv[256]; __shared__ int sni[256];
    spv[tid] = bpv; spi[tid] = bpi; snv[tid] = bnv; sni[tid] = bni;
    __syncthreads();
    for (int st = 128; st > 0; st >>= 1) {
        if (tid < st) {
            float ov = spv[tid + st]; int oi = spi[tid + st];
            if (ov > spv[tid] || (ov == spv[tid] && oi < spi[tid])) { spv[tid] = ov; spi[tid] = oi; }
            float nv = snv[tid + st]; int ni2 = sni[tid + st];
            if (nv < snv[tid] || (nv == snv[tid] && ni2 < sni[tid])) { snv[tid] = nv; sni[tid] = ni2; }
        }
        __syncthreads();
    }
    if (tid == 0) { g_hp[i] = spi[0]; g_hn[i] = sni[0]; }
}

// ===========================================================================
// Kernel 4: attention + distance, HALF-TILE blocks for 2 blocks/SM overlap.
// 4096 blocks x 128 threads; each block does 64 rows of one (sample,pos/neg)
// tile. 8x8 k-packed microtile (proven 1:1 crossbar:fma shape), register
// softmax, fused distance. smem: b1 = A-half natural -> P-half natural
// (64 rows); b2 = O natural -> O^T (128 rows). 99.8 KB/block.
// ===========================================================================
__global__ __launch_bounds__(128, 2)
void attn_kernel(const float* __restrict__ X) {
    extern __shared__ __align__(16) float sm[];
    float* b1 = sm;              // A-half natural -> P-half natural (64 x SA)
    float* b2 = sm + 64 * SA;    // O natural -> O^T (128 x SA)
    __shared__ float xch[128];

    const int tid  = threadIdx.x;
    const int tx   = tid & 15;      // j/c index: tx + 16n, n<8
    const int ty   = tid >> 4;      // 0..7; local row i = ty + 8m, m<8
    const int blk  = blockIdx.x;
    const int half = blk & 1;
    const int pr   = blk >> 1;      // pair index 0..2047
    const int bb   = pr >> 1;
    const int oidx = (pr & 1) ? g_hn[bb] : g_hp[bb];
    const float* Ag = X + (size_t)bb * D + (size_t)(half * 64) * WH;  // our 64 rows
    const float* Og = X + (size_t)oidx * D;

    // ---- phase 1: A-half natural -> b1 (64 rows), O natural -> b2 ----
    for (int u = tid; u < 2048; u += 128) {       // 2048 float4 = 64x128 A
        int rr = u >> 5;
        int c4 = (u & 31) << 2;
        float4 va = *(const float4*)(Ag + rr * WH + c4);
        float* d1 = &b1[rr * SA + c4];
        *(float2*)(d1 + 0) = make_float2(va.x, va.y);
        *(float2*)(d1 + 2) = make_float2(va.z, va.w);
    }
    for (int u = tid; u < 4096; u += 128) {       // 4096 float4 = 128x128 O
        int rr = u >> 5;
        int c4 = (u & 31) << 2;
        float4 vo = *(const float4*)(Og + rr * WH + c4);
        float* d2 = &b2[rr * SA + c4];
        *(float2*)(d2 + 0) = make_float2(vo.x, vo.y);
        *(float2*)(d2 + 2) = make_float2(vo.z, vo.w);
    }
    __syncthreads();

    ull acc[8][8];

    // ---- phase 2: GEMM1  S[i][j] = sum_c A[i][c] O[j][c]; gram-style ----
#pragma unroll
    for (int m = 0; m < 8; m++)
#pragma unroll
        for (int n = 0; n < 8; n++) acc[m][n] = 0ull;

#pragma unroll 1
    for (int ch = 0; ch < 8; ch++) {
        const float* p1r = &b1[ty * SA + 16 * ch];
        const float* p2r = &b2[tx * SA + 16 * ch];
#pragma unroll
        for (int kp = 0; kp < 8; kp++) {
            ull av[8], bv[8];
#pragma unroll
            for (int m = 0; m < 8; m++)
                av[m] = *(const ull*)(p1r + (8 * m) * SA + 2 * kp);
#pragma unroll
            for (int n = 0; n < 8; n++)
                bv[n] = *(const ull*)(p2r + (16 * n) * SA + 2 * kp);
#pragma unroll
            for (int m = 0; m < 8; m++)
#pragma unroll
                for (int n = 0; n < 8; n++) ffma2(acc[m][n], av[m], bv[n]);
        }
    }

    // ---- phase 3: register softmax along j (16 threads/row = half-warp) ----
    const float scale = 0.088388347648318447f;  // 1/sqrt(128)
    float p[8][8];
#pragma unroll
    for (int m = 0; m < 8; m++) {
        float rmax = -3.0e38f;
#pragma unroll
        for (int n = 0; n < 8; n++) {
            p[m][n] = f2sum(acc[m][n]) * scale;
            rmax = fmaxf(rmax, p[m][n]);
        }
#pragma unroll
        for (int s = 1; s < 16; s <<= 1)
            rmax = fmaxf(rmax, __shfl_xor_sync(0xFFFFFFFFu, rmax, s));
        float rsum = 0.f;
#pragma unroll
        for (int n = 0; n < 8; n++) {
            p[m][n] = __expf(p[m][n] - rmax);
            rsum += p[m][n];
        }
#pragma unroll
        for (int s = 1; s < 16; s <<= 1)
            rsum += __shfl_xor_sync(0xFFFFFFFFu, rsum, s);
        float rinv = 1.f / rsum;
#pragma unroll
        for (int n = 0; n < 8; n++) p[m][n] *= rinv;
    }
    __syncthreads();  // all GEMM1 smem reads done before overwrite

    // ---- phase 4: P-half natural -> b1; O^T (from gmem, L2-hot) -> b2 ----
#pragma unroll
    for (int m = 0; m < 8; m++)
#pragma unroll
        for (int n = 0; n < 8; n++)
            b1[(ty + 8 * m) * SA + tx + 16 * n] = p[m][n];
    for (int u = tid; u < 4096; u += 128) {
        int rr = u >> 5;
        int c4 = (u & 31) << 2;
        float4 vo = *(const float4*)(Og + rr * WH + c4);
        b2[(c4 + 0) * SA + rr] = vo.x;
        b2[(c4 + 1) * SA + rr] = vo.y;
        b2[(c4 + 2) * SA + rr] = vo.z;
        b2[(c4 + 3) * SA + rr] = vo.w;
    }
    __syncthreads();

    // ---- phase 5: GEMM2  M[i][c] = sum_j P[i][j] O^T[c][j]; gram-style ----
#pragma unroll
    for (int m = 0; m < 8; m++)
#pragma unroll
        for (int n = 0; n < 8; n++) acc[m][n] = 0ull;

#pragma unroll 1
    for (int ch = 0; ch < 8; ch++) {
        const float* p1r = &b1[ty * SA + 16 * ch];
        const float* p2r = &b2[tx * SA + 16 * ch];
#pragma unroll
        for (int jp = 0; jp < 8; jp++) {
            ull pv[8], ov[8];
#pragma unroll
            for (int m = 0; m < 8; m++)
                pv[m] = *(const ull*)(p1r + (8 * m) * SA + 2 * jp);
#pragma unroll
            for (int n = 0; n < 8; n++)
                ov[n] = *(const ull*)(p2r + (16 * n) * SA + 2 * jp);
#pragma unroll
            for (int m = 0; m < 8; m++)
#pragma unroll
                for (int n = 0; n < 8; n++) ffma2(acc[m][n], pv[m], ov[n]);
        }
    }

    // ---- phase 6: fused distance (A from gmem, L2-hot) + block reduce ----
    float dsum = 0.f;
#pragma unroll
    for (int m = 0; m < 8; m++)
#pragma unroll
        for (int n = 0; n < 8; n++) {
            float a = Ag[(ty + 8 * m) * WH + tx + 16 * n];
            float d = a - f2sum(acc[m][n]);
            dsum += d * d;
        }
    xch[tid] = dsum;
    __syncthreads();
    for (int st = 64; st > 0; st >>= 1) {
        if (tid < st) xch[tid] += xch[tid + st];
        __syncthreads();
    }
    if (tid == 0) g_dd[blk] = xch[0];
}

// ===========================================================================
// Kernel 5: final margin ranking loss (sums the two half-block partials)
// ===========================================================================
__global__ void loss_kernel(float* __restrict__ out) {
    int tid = threadIdx.x;
    float s = 0.f;
    for (int b = tid; b < N_SAMP; b += 256) {
        float dap = sqrtf(g_dd[4 * b + 0] + g_dd[4 * b + 1]);
        float dan = sqrtf(g_dd[4 * b + 2] + g_dd[4 * b + 3]);
        float v = dap - dan + 0.3f;
        s += (v > 0.f) ? v : 0.f;
    }
    __shared__ float red[256];
    red[tid] = s;
    __syncthreads();
    for (int st = 128; st > 0; st >>= 1) {
        if (tid < st) red[tid] += red[tid + st];
        __syncthreads();
    }
    if (tid == 0) out[0] = red[0] * (1.0f / (float)N_SAMP);
}

// ===========================================================================
extern "C" void kernel_launch(void* const* d_in, const int* in_sizes, int n_in,
                              void* d_out, int out_size) {
    const float* X;
    const int*   T;
    if (n_in >= 2 && in_sizes[0] == N_SAMP && in_sizes[1] != N_SAMP) {
        T = (const int*)d_in[0];
        X = (const float*)d_in[1];
    } else {
        X = (const float*)d_in[0];
        T = (const int*)d_in[1];
    }

    const int smem_attn = (64 + 128) * SA * (int)sizeof(float);  // 99840 B
    cudaFuncSetAttribute(attn_kernel, cudaFuncAttributeMaxDynamicSharedMemorySize,
                         smem_attn);

    gram_f2<<<144, 256>>>(X);
    gram_reduce<<<36, 256>>>();
    mine_kernel<<<N_SAMP, 256>>>(T);
    attn_kernel<<<4 * N_SAMP, 128, smem_attn>>>(X);
    loss_kernel<<<1, 256>>>((float*)d_out);
}